// round 15
// baseline (speedup 1.0000x reference)
#include <cuda_runtime.h>

#define DIM 4096
#define NQ 12
#define DEPTH 4

// sigma (gather form of the CNOT ring), GF(2)-linear, verified R1-R14.
__host__ __device__ __forceinline__ constexpr int sig(int x) {
    int r = (x ^ (x >> 1)) & 0x3FF;
    r |= (((x >> 10) ^ (x >> 11) ^ x) & 1) << 10;
    r |= (((x >> 11) ^ x) & 1) << 11;
    return r;
}
// sigma^{-1} (scatter-side fusion), verified R9-R14.
__host__ __device__ __forceinline__ constexpr int sig_inv(int x) {
    int y = 0, suf = 0;
    for (int i = 11; i >= 1; --i) {
        suf ^= (x >> i) & 1;
        if (i <= 10) y |= suf << i;
    }
    const int all = suf ^ (x & 1);
    y |= all;
    y |= (all ^ ((x >> 11) & 1)) << 11;
    return y;
}
// R2-champion placements (kernel passed at 7.84us with these):
__host__ __device__ __forceinline__ constexpr int pp(int y) {
    return y ^ ((y >> 5) & 1) ^ (((y >> 7) & 1) << 1) ^ (((y >> 6) & 1) << 2);
}
__host__ __device__ __forceinline__ constexpr int qq(int y) {
    return y ^ (((y >> 8) ^ (y >> 6)) & 1) ^ (((y >> 7) & 1) << 1)
             ^ (((y >> 5) & 1) << 2) ^ (((y >> 6) & 1) << 3);
}
// Layout-B k-bit embedding: k0..k2 -> index bits 9..11, k3 -> bit 8
__host__ __device__ __forceinline__ constexpr int kbB(int k) {
    return ((k & 7) << 9) | (((k >> 3) & 1) << 8);
}
// sig_inv(kbB(k)) basis images (verified R10/R12/R14 passing kernels):
//  i bit9 -> 0xBFF, bit10 -> 0xFFF, bit11 -> 0x7FF, bit8 -> 0x9FF
__host__ __device__ __forceinline__ constexpr int SIB(int k) {
    return ((k & 1) ? 0xBFF : 0) ^ ((k & 2) ? 0xFFF : 0)
         ^ ((k & 4) ? 0x7FF : 0) ^ ((k & 8) ? 0x9FF : 0);
}

__global__ __launch_bounds__(256, 1)
void qsim_kernel(const float* __restrict__ x, const float* __restrict__ theta,
                 const float* __restrict__ w, const float* __restrict__ b,
                 float* __restrict__ out) {
    __shared__ float S0[DIM];   // inter-layer buffer (pp placement)
    __shared__ float S1[DIM];   // intra-layer buffer (qq placement)
    __shared__ float CS[DEPTH * NQ];
    __shared__ float SN[DEPTH * NQ];
    __shared__ float red[16];

    const int tid = threadIdx.x;
    const int lane = tid & 31;
    const int wid = tid >> 5;   // 0..7

    // half-angle tables: a[d][q] = (theta[d][q] + 0.1*x[q]) / 2
    if (tid < DEPTH * NQ) {
        const int q = tid % NQ;
        float s, c;
        __sincosf(0.5f * (theta[tid] + 0.1f * x[q]), &s, &c);
        CS[tid] = c;
        SN[tid] = s;
    }

    // Layout A: j = wid<<9 | lane<<4 | k   (k bits 0-3 = qubits 11..8,
    //            lane bits 4-8 = qubits 7..3, wid bits 9-11 = qubits 2..0)
    // Layout B: i = kbB(k) | lane<<3 | wid
    const int baseA = (wid << 9) | (lane << 4);
    const int baseB = (lane << 3) | wid;
    const int ldA = pp(sig(baseA));   // ^ pp(sig(k))   [A gather, prev ring fused]
    const int stA = qq(baseA);        // ^ k            [A scatter]
    const int ldB = qq(baseB);        // ^ qq(kbB(k))   [B gather]
    const int stB = pp(baseB);        // ^ kbB(k)       [B scatter]
    const int gOut = sig_inv(baseB);  // ^ SIB(k)       [readout scatter, ring-3 fused]

    float v[16];
    __syncthreads();                  // tables ready

    // ============ Layer 0 + ring 0 folded into layer-1 pass-A registers ==========
    // postRing0[j] = prod0[sig(j)]; sig linear => uk = sig(baseA) ^ sig(k),
    // sig(k) = gray(k) on bits 0-3 plus (k&1) on bits 10,11.
    {
        const int u0 = sig(baseA);
        float Pfix = 1.f;
#pragma unroll
        for (int bp = 4; bp <= 9; ++bp)           // bits 4-9 -> qubits 7..2 (k-invariant)
            Pfix *= ((u0 >> bp) & 1) ? SN[11 - bp] : CS[11 - bp];
        const int b10 = (u0 >> 10) & 1, b11 = (u0 >> 11) & 1;
        const float PEa = Pfix * (b10 ? SN[1] : CS[1]) * (b11 ? SN[0] : CS[0]);
        const float PEb = Pfix * (b10 ? CS[1] : SN[1]) * (b11 ? CS[0] : SN[0]);
        const float f11 = (u0 & 1) ? SN[11] : CS[11], f11x = (u0 & 1) ? CS[11] : SN[11];
        const float f10 = (u0 & 2) ? SN[10] : CS[10], f10x = (u0 & 2) ? CS[10] : SN[10];
        const float f9  = (u0 & 4) ? SN[9]  : CS[9],  f9x  = (u0 & 4) ? CS[9]  : SN[9];
        const float f8  = (u0 & 8) ? SN[8]  : CS[8],  f8x  = (u0 & 8) ? CS[8]  : SN[8];
#pragma unroll
        for (int k = 0; k < 16; ++k) {
            const int cg = (k ^ (k >> 1)) & 0xF;  // compile-time gray(k)
            const float lo = ((cg & 1) ? f11x : f11) * ((cg & 2) ? f10x : f10);
            const float hi = ((cg & 4) ? f9x : f9) * ((cg & 8) ? f8x : f8);
            v[k] = ((k & 1) ? PEb : PEa) * lo * hi;
        }
    }

    // ============ Layers 1..3 (R2-champion bodies) ============
    for (int d = 1; d < DEPTH; ++d) {
        const float* C = CS + d * NQ;
        const float* Sn = SN + d * NQ;

        // ---- Pass A: gather (d>1; ring fused; d==1 regs already hold state),
        //      rotate qubits 11..8 (k bits) + 7..3 (lane shfl), scatter to S1.
        if (d > 1) {
#pragma unroll
            for (int k = 0; k < 16; ++k) v[k] = S0[ldA ^ pp(sig(k))];
        }
#pragma unroll
        for (int rb = 0; rb < 4; ++rb) {          // k bit rb -> qubit 11-rb
            const int m = 1 << rb;
            const float c = C[11 - rb], s = Sn[11 - rb];
#pragma unroll
            for (int k = 0; k < 16; ++k)
                if (!(k & m)) {
                    const float lo = v[k], hi = v[k | m];
                    v[k]     = fmaf(c, lo, -s * hi);
                    v[k | m] = fmaf(s, lo,  c * hi);
                }
        }
#pragma unroll
        for (int bs = 0; bs < 5; ++bs) {          // lane bit bs -> qubit 7-bs
            const int m = 1 << bs;
            const float c = C[7 - bs], s = Sn[7 - bs];
            const float se = (lane & m) ? s : -s;
#pragma unroll
            for (int k = 0; k < 16; ++k) {
                const float o = __shfl_xor_sync(0xffffffffu, v[k], m);
                v[k] = fmaf(c, v[k], se * o);
            }
        }
#pragma unroll
        for (int k = 0; k < 16; ++k) S1[stA ^ k] = v[k];
        __syncthreads();

        // ---- Pass B: gather from S1, rotate qubits 2,1,0 (k bits); store plain
        //      to S0 (ring fused on next consumer) except layer 3 keeps regs.
#pragma unroll
        for (int k = 0; k < 16; ++k) v[k] = S1[ldB ^ qq(kbB(k))];

#pragma unroll
        for (int rb = 0; rb < 3; ++rb) {          // k bit rb -> bit 9+rb -> qubit 2-rb
            const int m = 1 << rb;
            const float c = C[2 - rb], s = Sn[2 - rb];
#pragma unroll
            for (int k = 0; k < 16; ++k)
                if (!(k & m)) {
                    const float lo = v[k], hi = v[k | m];
                    v[k]     = fmaf(c, lo, -s * hi);
                    v[k | m] = fmaf(s, lo,  c * hi);
                }
        }
        if (d < DEPTH - 1) {
#pragma unroll
            for (int k = 0; k < 16; ++k) S0[stB ^ kbB(k)] = v[k];
            __syncthreads();
        }
    }

    // ============ Readout folded into layer-3 pass-B registers ============
    // v[k] = pre-ring-3 value at i = baseB|kbB(k); final index g = sig_inv(i).
    float a0 = 0.f, a1 = 0.f;
#pragma unroll
    for (int k = 0; k < 16; ++k) {
        const int g = gOut ^ SIB(k);
        out[2 + g] = v[k];                 // scattered but bijective
        const float p = v[k] * v[k];
        a0 = fmaf(p, w[g], a0);
        a1 = fmaf(p, w[DIM + g], a1);
    }
#pragma unroll
    for (int o = 16; o > 0; o >>= 1) {
        a0 += __shfl_down_sync(0xffffffffu, a0, o);
        a1 += __shfl_down_sync(0xffffffffu, a1, o);
    }
    if (lane == 0) { red[wid] = a0; red[8 + wid] = a1; }
    __syncthreads();
    if (wid == 0 && lane < 16) {
        float rr = (lane < 8) ? red[lane] : red[8 + (lane & 7)];
#pragma unroll
        for (int o = 4; o > 0; o >>= 1)
            rr += __shfl_down_sync(0x0000ffffu, rr, o);
        if (lane == 0) out[0] = rr + b[0];
        if (lane == 8) out[1] = rr + b[1];
    }
}

extern "C" void kernel_launch(void* const* d_in, const int* in_sizes, int n_in,
                              void* d_out, int out_size) {
    const float* x = nullptr;
    const float* th = nullptr;
    const float* w = nullptr;
    const float* b = nullptr;
    for (int i = 0; i < n_in; ++i) {
        const int s = in_sizes[i];
        if (s == NQ) x = (const float*)d_in[i];
        else if (s == DEPTH * NQ) th = (const float*)d_in[i];
        else if (s == 2 * DIM) w = (const float*)d_in[i];
        else if (s == 2) b = (const float*)d_in[i];
    }
    qsim_kernel<<<1, 256>>>(x, th, w, b, (float*)d_out);
}

// round 17
// speedup vs baseline: 2.3201x; 2.3201x over previous
#include <cuda_runtime.h>

#define DIM 4096
#define NQ 12
#define DEPTH 4

// sigma (gather form of the CNOT ring), GF(2)-linear, verified R1-R15.
__host__ __device__ __forceinline__ constexpr int sig(int x) {
    int r = (x ^ (x >> 1)) & 0x3FF;
    r |= (((x >> 10) ^ (x >> 11) ^ x) & 1) << 10;
    r |= (((x >> 11) ^ x) & 1) << 11;
    return r;
}
// R2-champion placements (7.84us kernel measured with these):
__host__ __device__ __forceinline__ constexpr int pp(int y) {
    return y ^ ((y >> 5) & 1) ^ (((y >> 7) & 1) << 1) ^ (((y >> 6) & 1) << 2);
}
__host__ __device__ __forceinline__ constexpr int qq(int y) {
    return y ^ (((y >> 8) ^ (y >> 6)) & 1) ^ (((y >> 7) & 1) << 1)
             ^ (((y >> 5) & 1) << 2) ^ (((y >> 6) & 1) << 3);
}
// Layout-B k-bit embedding: k0..k2 -> index bits 9..11, k3 -> bit 8
__host__ __device__ __forceinline__ constexpr int kbB(int k) {
    return ((k & 7) << 9) | (((k >> 3) & 1) << 8);
}

__global__ __launch_bounds__(256, 1)
void qsim_kernel(const float* __restrict__ x, const float* __restrict__ theta,
                 const float* __restrict__ w, const float* __restrict__ b,
                 float* __restrict__ out) {
    __shared__ float S0[DIM];   // inter-layer buffer (pp placement)
    __shared__ float S1[DIM];   // intra-layer buffer (qq placement)
    __shared__ float CS[DEPTH * NQ];
    __shared__ float SN[DEPTH * NQ];
    __shared__ float red[16];

    const int tid = threadIdx.x;
    const int lane = tid & 31;
    const int wid = tid >> 5;   // 0..7

    // half-angle tables: a[d][q] = (theta[d][q] + 0.1*x[q]) / 2
    if (tid < DEPTH * NQ) {
        const int q = tid % NQ;
        float s, c;
        __sincosf(0.5f * (theta[tid] + 0.1f * x[q]), &s, &c);
        CS[tid] = c;
        SN[tid] = s;
    }

    // Layout A: j = wid<<9 | lane<<4 | k   (k bits 0-3 = qubits 11..8,
    //            lane bits 4-8 = qubits 7..3, wid bits 9-11 = qubits 2..0)
    // Layout B: i = kbB(k) | lane<<3 | wid
    const int baseA = (wid << 9) | (lane << 4);
    const int baseB = (lane << 3) | wid;
    const int ldA = pp(sig(baseA));   // ^ pp(sig(k))   [A gather, prev ring fused]
    const int stA = qq(baseA);        // ^ k            [A scatter]
    const int ldB = qq(baseB);        // ^ qq(kbB(k))   [B gather]
    const int stB = pp(baseB);        // ^ kbB(k)       [B scatter]

    float v[16];
    __syncthreads();                  // tables ready

    // ============ Layer 0 + ring 0 folded into layer-1 pass-A registers ==========
    // postRing0[j] = prod0[sig(j)]; sig linear => uk = sig(baseA) ^ sig(k),
    // sig(k) = gray(k) on bits 0-3 plus (k&1) on bits 10,11. (verified R15: passed)
    {
        const int u0 = sig(baseA);
        float Pfix = 1.f;
#pragma unroll
        for (int bp = 4; bp <= 9; ++bp)           // bits 4-9 -> qubits 7..2 (k-invariant)
            Pfix *= ((u0 >> bp) & 1) ? SN[11 - bp] : CS[11 - bp];
        const int b10 = (u0 >> 10) & 1, b11 = (u0 >> 11) & 1;
        const float PEa = Pfix * (b10 ? SN[1] : CS[1]) * (b11 ? SN[0] : CS[0]);
        const float PEb = Pfix * (b10 ? CS[1] : SN[1]) * (b11 ? CS[0] : SN[0]);
        const float f11 = (u0 & 1) ? SN[11] : CS[11], f11x = (u0 & 1) ? CS[11] : SN[11];
        const float f10 = (u0 & 2) ? SN[10] : CS[10], f10x = (u0 & 2) ? CS[10] : SN[10];
        const float f9  = (u0 & 4) ? SN[9]  : CS[9],  f9x  = (u0 & 4) ? CS[9]  : SN[9];
        const float f8  = (u0 & 8) ? SN[8]  : CS[8],  f8x  = (u0 & 8) ? CS[8]  : SN[8];
#pragma unroll
        for (int k = 0; k < 16; ++k) {
            const int cg = (k ^ (k >> 1)) & 0xF;  // compile-time gray(k)
            const float lo = ((cg & 1) ? f11x : f11) * ((cg & 2) ? f10x : f10);
            const float hi = ((cg & 4) ? f9x : f9) * ((cg & 8) ? f8x : f8);
            v[k] = ((k & 1) ? PEb : PEa) * lo * hi;
        }
    }

    // ============ Layers 1..3 (R2-champion bodies; d-loop fully unrolled so
    //              the d==1 gather-skip is compile-time) ============
#pragma unroll
    for (int d = 1; d < DEPTH; ++d) {
        const float* C = CS + d * NQ;
        const float* Sn = SN + d * NQ;

        // ---- Pass A: gather (d>1; prev ring fused; d==1 regs hold state),
        //      rotate qubits 11..8 (k bits) + 7..3 (lane shfl), scatter to S1.
        if (d > 1) {
#pragma unroll
            for (int k = 0; k < 16; ++k) v[k] = S0[ldA ^ pp(sig(k))];
        }
#pragma unroll
        for (int rb = 0; rb < 4; ++rb) {          // k bit rb -> qubit 11-rb
            const int m = 1 << rb;
            const float c = C[11 - rb], s = Sn[11 - rb];
#pragma unroll
            for (int k = 0; k < 16; ++k)
                if (!(k & m)) {
                    const float lo = v[k], hi = v[k | m];
                    v[k]     = fmaf(c, lo, -s * hi);
                    v[k | m] = fmaf(s, lo,  c * hi);
                }
        }
#pragma unroll
        for (int bs = 0; bs < 5; ++bs) {          // lane bit bs -> qubit 7-bs
            const int m = 1 << bs;
            const float c = C[7 - bs], s = Sn[7 - bs];
            const float se = (lane & m) ? s : -s;
#pragma unroll
            for (int k = 0; k < 16; ++k) {
                const float o = __shfl_xor_sync(0xffffffffu, v[k], m);
                v[k] = fmaf(c, v[k], se * o);
            }
        }
#pragma unroll
        for (int k = 0; k < 16; ++k) S1[stA ^ k] = v[k];
        __syncthreads();

        // ---- Pass B: gather from S1, rotate qubits 2,1,0 (k bits),
        //      scatter plain to S0 (ring fused on next consumer).
#pragma unroll
        for (int k = 0; k < 16; ++k) v[k] = S1[ldB ^ qq(kbB(k))];

#pragma unroll
        for (int rb = 0; rb < 3; ++rb) {          // k bit rb -> bit 9+rb -> qubit 2-rb
            const int m = 1 << rb;
            const float c = C[2 - rb], s = Sn[2 - rb];
#pragma unroll
            for (int k = 0; k < 16; ++k)
                if (!(k & m)) {
                    const float lo = v[k], hi = v[k | m];
                    v[k]     = fmaf(c, lo, -s * hi);
                    v[k | m] = fmaf(s, lo,  c * hi);
                }
        }
#pragma unroll
        for (int k = 0; k < 16; ++k) S0[stB ^ kbB(k)] = v[k];
        __syncthreads();
    }

    // ============ Readout (R2 form: final ring fused into coalesced gather) ======
    // r = wid<<9 | k<<5 | lane  (coalesced global access; w loads coalesced)
    const int baseR = (wid << 9) | lane;
    const int ldR = pp(sig(baseR));
    float a0 = 0.f, a1 = 0.f;
#pragma unroll
    for (int k = 0; k < 16; ++k) {
        const int r = baseR | (k << 5);
        const float vv = S0[ldR ^ pp(sig(k << 5))];
        out[2 + r] = vv;
        const float p = vv * vv;
        a0 = fmaf(p, w[r], a0);
        a1 = fmaf(p, w[DIM + r], a1);
    }
#pragma unroll
    for (int o = 16; o > 0; o >>= 1) {
        a0 += __shfl_down_sync(0xffffffffu, a0, o);
        a1 += __shfl_down_sync(0xffffffffu, a1, o);
    }
    if (lane == 0) { red[wid] = a0; red[8 + wid] = a1; }
    __syncthreads();
    if (wid == 0 && lane < 16) {
        float rr = (lane < 8) ? red[lane] : red[8 + (lane & 7)];
#pragma unroll
        for (int o = 4; o > 0; o >>= 1)
            rr += __shfl_down_sync(0x0000ffffu, rr, o);
        if (lane == 0) out[0] = rr + b[0];
        if (lane == 8) out[1] = rr + b[1];
    }
}

extern "C" void kernel_launch(void* const* d_in, const int* in_sizes, int n_in,
                              void* d_out, int out_size) {
    const float* x = nullptr;
    const float* th = nullptr;
    const float* w = nullptr;
    const float* b = nullptr;
    for (int i = 0; i < n_in; ++i) {
        const int s = in_sizes[i];
        if (s == NQ) x = (const float*)d_in[i];
        else if (s == DEPTH * NQ) th = (const float*)d_in[i];
        else if (s == 2 * DIM) w = (const float*)d_in[i];
        else if (s == 2) b = (const float*)d_in[i];
    }
    qsim_kernel<<<1, 256>>>(x, th, w, b, (float*)d_out);
}